// round 7
// baseline (speedup 1.0000x reference)
#include <cuda_runtime.h>

#define NUM_NODES 1000000
#define NUM_EDGES 16000000
#define F  6
#define FP 8               // padded row: 32B = one L2 sector
#define SCAN_BLK 1024
#define NBLK ((NUM_NODES + SCAN_BLK - 1) / SCAN_BLK)   // 977
#define GBLK 256           // nodes per gather block
#define SMEM_EDGES 8192    // staged edge capacity (mean 4096, Poisson-tight)

// Scratch (device globals; no allocation anywhere).
__device__ __align__(128) float g_x8 [NUM_NODES * FP];   // padded x (lanes 6,7 = 0)
__device__ __align__(128) float g_h8 [NUM_NODES * FP];   // padded layer-1 output
__device__ __align__(128) int   g_sorted[NUM_EDGES];     // src ids grouped by dst
__device__ __align__(128) int   g_cnt   [NUM_NODES];     // in-degree
__device__ __align__(128) int   g_rowst [NUM_NODES];     // exclusive scan of cnt
__device__ __align__(128) int   g_cursor[NUM_NODES];     // mutable copy for reorder
__device__ __align__(128) int   g_bsum  [NBLK];
__device__ int g_idx_is32;

// ---------------------------------------------------------------------------
__global__ void detect_kernel(const long long* __restrict__ ei) {
    __shared__ int bad;
    if (threadIdx.x == 0) bad = 0;
    __syncthreads();
    #pragma unroll
    for (int r = 0; r < 16; r++) {
        long long v = ei[threadIdx.x + r * 256];
        if ((unsigned long long)v >= (unsigned long long)NUM_NODES) bad = 1;
    }
    __syncthreads();
    if (threadIdx.x == 0) g_idx_is32 = bad;
}

// ---------------------------------------------------------------------------
__global__ void prep_kernel(const float* __restrict__ x) {
    int i = blockIdx.x * blockDim.x + threadIdx.x;
    if (i >= NUM_NODES) return;
    const float* xr = x + (size_t)i * F;
    float4* px = reinterpret_cast<float4*>(g_x8 + (size_t)i * FP);
    px[0] = make_float4(xr[0], xr[1], xr[2], xr[3]);
    px[1] = make_float4(xr[4], xr[5], 0.f, 0.f);
    g_cnt[i] = 0;
}

// ---------------------------------------------------------------------------
__global__ void hist_kernel(const void* __restrict__ ei) {
    int i = blockIdx.x * blockDim.x + threadIdx.x;
    if (i >= NUM_EDGES / 4) return;
    unsigned d[4];
    if (g_idx_is32) {
        const int* dst = (const int*)ei + NUM_EDGES;
        int4 dv = __ldcs(reinterpret_cast<const int4*>(dst) + i);
        d[0] = dv.x; d[1] = dv.y; d[2] = dv.z; d[3] = dv.w;
    } else {
        const long long* dst = (const long long*)ei + NUM_EDGES;
        longlong2 d0 = __ldcs(reinterpret_cast<const longlong2*>(dst) + 2 * i);
        longlong2 d1 = __ldcs(reinterpret_cast<const longlong2*>(dst) + 2 * i + 1);
        d[0] = (unsigned)d0.x; d[1] = (unsigned)d0.y;
        d[2] = (unsigned)d1.x; d[3] = (unsigned)d1.y;
    }
    #pragma unroll
    for (int e = 0; e < 4; e++)
        if (d[e] < NUM_NODES) atomicAdd(&g_cnt[d[e]], 1);
}

// ---------------------------------------------------------------------------
// 3-kernel exclusive scan of g_cnt -> g_rowst (+ g_cursor copy).
// ---------------------------------------------------------------------------
__global__ void scan1_kernel() {
    __shared__ int s[SCAN_BLK];
    int t = threadIdx.x;
    int gid = blockIdx.x * SCAN_BLK + t;
    int v = (gid < NUM_NODES) ? g_cnt[gid] : 0;
    s[t] = v;
    for (int off = 1; off < SCAN_BLK; off <<= 1) {
        __syncthreads();
        int add = (t >= off) ? s[t - off] : 0;
        __syncthreads();
        s[t] += add;
    }
    __syncthreads();
    if (gid < NUM_NODES) g_rowst[gid] = s[t] - v;
    if (t == SCAN_BLK - 1) g_bsum[blockIdx.x] = s[t];
}

__global__ void scan2_kernel() {
    __shared__ int s[SCAN_BLK];
    int t = threadIdx.x;
    int v = (t < NBLK) ? g_bsum[t] : 0;
    s[t] = v;
    for (int off = 1; off < SCAN_BLK; off <<= 1) {
        __syncthreads();
        int add = (t >= off) ? s[t - off] : 0;
        __syncthreads();
        s[t] += add;
    }
    __syncthreads();
    if (t < NBLK) g_bsum[t] = s[t] - v;
}

__global__ void scan3_kernel() {
    int gid = blockIdx.x * SCAN_BLK + threadIdx.x;
    if (gid >= NUM_NODES) return;
    int r = g_rowst[gid] + g_bsum[blockIdx.x];
    g_rowst[gid]  = r;
    g_cursor[gid] = r;
}

// ---------------------------------------------------------------------------
__global__ void reorder_kernel(const void* __restrict__ ei) {
    int i = blockIdx.x * blockDim.x + threadIdx.x;
    if (i >= NUM_EDGES / 4) return;
    unsigned s[4], d[4];
    if (g_idx_is32) {
        const int* src = (const int*)ei;
        const int* dst = src + NUM_EDGES;
        int4 sv = __ldcs(reinterpret_cast<const int4*>(src) + i);
        int4 dv = __ldcs(reinterpret_cast<const int4*>(dst) + i);
        s[0] = sv.x; s[1] = sv.y; s[2] = sv.z; s[3] = sv.w;
        d[0] = dv.x; d[1] = dv.y; d[2] = dv.z; d[3] = dv.w;
    } else {
        const long long* src = (const long long*)ei;
        const long long* dst = src + NUM_EDGES;
        longlong2 s0 = __ldcs(reinterpret_cast<const longlong2*>(src) + 2 * i);
        longlong2 s1 = __ldcs(reinterpret_cast<const longlong2*>(src) + 2 * i + 1);
        longlong2 d0 = __ldcs(reinterpret_cast<const longlong2*>(dst) + 2 * i);
        longlong2 d1 = __ldcs(reinterpret_cast<const longlong2*>(dst) + 2 * i + 1);
        s[0] = (unsigned)s0.x; s[1] = (unsigned)s0.y; s[2] = (unsigned)s1.x; s[3] = (unsigned)s1.y;
        d[0] = (unsigned)d0.x; d[1] = (unsigned)d0.y; d[2] = (unsigned)d1.x; d[3] = (unsigned)d1.y;
    }
    #pragma unroll
    for (int e = 0; e < 4; e++) {
        if (s[e] < NUM_NODES && d[e] < NUM_NODES) {
            int p = atomicAdd(&g_cursor[d[e]], 1);
            g_sorted[p] = (int)s[e];
        }
    }
}

// ---------------------------------------------------------------------------
// Fused gather + transform. 256 nodes per block. The block's edge lists are
// CONTIGUOUS in g_sorted -> cooperatively stage them into SMEM (coalesced),
// then each thread scans its segment via LDS. No atomics, no uncoalesced
// index reads. PHASE 0: x8 -> h8. PHASE 1: h8 -> argmax/one-hot -> out.
// ---------------------------------------------------------------------------
template <int PHASE>
__global__ void gather_kernel(const float* __restrict__ Wrel,
                              const float* __restrict__ Wroot,
                              const float* __restrict__ b,
                              float* __restrict__ out) {
    __shared__ float swr[36], swo[36], sb[6];
    __shared__ int   s_edges[SMEM_EDGES];
    __shared__ int   s_info[2];     // bstart, total (or -1 = fallback)

    int t = threadIdx.x;
    if (t < 36)        swr[t]      = Wrel[t];
    else if (t < 72)   swo[t - 36] = Wroot[t - 36];
    else if (t < 78)   sb[t - 72]  = b[t - 72];

    int n0 = blockIdx.x * GBLK;
    int n  = n0 + t;
    bool valid = (n < NUM_NODES);

    int myStart = valid ? g_rowst[n] : 0;
    int myDeg   = valid ? g_cnt[n]   : 0;

    if (t == 0) {
        int nL = min(n0 + GBLK, NUM_NODES) - 1;        // last valid node
        int bstart = g_rowst[n0];
        int bend   = g_rowst[nL] + g_cnt[nL];
        int total  = bend - bstart;
        s_info[0] = bstart;
        s_info[1] = (total <= SMEM_EDGES) ? total : -1;
    }
    __syncthreads();
    int bstart = s_info[0];
    int total  = s_info[1];

    if (total >= 0) {
        for (int k = t; k < total; k += GBLK)
            s_edges[k] = g_sorted[bstart + k];          // coalesced
    }
    __syncthreads();

    if (!valid) return;

    const float* feat = PHASE ? g_h8 : g_x8;
    float ag[6] = {0.f, 0.f, 0.f, 0.f, 0.f, 0.f};

    if (total >= 0) {
        int off = myStart - bstart;
        int j = 0;
        for (; j + 1 < myDeg; j += 2) {
            int s0 = s_edges[off + j];
            int s1 = s_edges[off + j + 1];
            const float* r0 = feat + (size_t)s0 * FP;
            const float* r1 = feat + (size_t)s1 * FP;
            float4 a0 = *reinterpret_cast<const float4*>(r0);
            float2 b0 = *reinterpret_cast<const float2*>(r0 + 4);
            float4 a1 = *reinterpret_cast<const float4*>(r1);
            float2 b1 = *reinterpret_cast<const float2*>(r1 + 4);
            ag[0] += a0.x + a1.x;  ag[1] += a0.y + a1.y;
            ag[2] += a0.z + a1.z;  ag[3] += a0.w + a1.w;
            ag[4] += b0.x + b1.x;  ag[5] += b0.y + b1.y;
        }
        if (j < myDeg) {
            int s0 = s_edges[off + j];
            const float* r0 = feat + (size_t)s0 * FP;
            float4 a0 = *reinterpret_cast<const float4*>(r0);
            float2 b0 = *reinterpret_cast<const float2*>(r0 + 4);
            ag[0] += a0.x; ag[1] += a0.y; ag[2] += a0.z;
            ag[3] += a0.w; ag[4] += b0.x; ag[5] += b0.y;
        }
    } else {
        // fallback (only if a block's edge list exceeds SMEM capacity)
        for (int j = 0; j < myDeg; j++) {
            int s0 = g_sorted[myStart + j];
            const float* r0 = feat + (size_t)s0 * FP;
            float4 a0 = *reinterpret_cast<const float4*>(r0);
            float2 b0 = *reinterpret_cast<const float2*>(r0 + 4);
            ag[0] += a0.x; ag[1] += a0.y; ag[2] += a0.z;
            ag[3] += a0.w; ag[4] += b0.x; ag[5] += b0.y;
        }
    }

    const float* xr = feat + (size_t)n * FP;
    float4 x0 = *reinterpret_cast<const float4*>(xr);
    float2 x1 = *reinterpret_cast<const float2*>(xr + 4);
    float xv[6] = {x0.x, x0.y, x0.z, x0.w, x1.x, x1.y};

    float h[6];
    #pragma unroll
    for (int k = 0; k < 6; k++) {
        float acc = sb[k];
        #pragma unroll
        for (int m = 0; m < 6; m++) {
            acc = fmaf(ag[m], swr[k * 6 + m], acc);
            acc = fmaf(xv[m], swo[k * 6 + m], acc);
        }
        h[k] = acc;
    }

    if (PHASE == 0) {
        float4* ph = reinterpret_cast<float4*>(g_h8 + (size_t)n * FP);
        ph[0] = make_float4(h[0], h[1], h[2], h[3]);
        ph[1] = make_float4(h[4], h[5], 0.f, 0.f);
    } else {
        int best = 0; float bv = h[0];
        #pragma unroll
        for (int k = 1; k < 6; k++)
            if (h[k] > bv) { bv = h[k]; best = k; }     // first-max = jnp.argmax
        float* po = out + (size_t)n * F;
        #pragma unroll
        for (int k = 0; k < 6; k++)
            po[k] = (k == best) ? 1.f : 0.f;
    }
}

extern "C" void kernel_launch(void* const* d_in, const int* in_sizes, int n_in,
                              void* d_out, int out_size) {
    const float* x      = (const float*)d_in[0];
    const void*  ei     = d_in[1];
    const float* Wrel1  = (const float*)d_in[2];
    const float* Wroot1 = (const float*)d_in[3];
    const float* b1     = (const float*)d_in[4];
    const float* Wrel2  = (const float*)d_in[5];
    const float* Wroot2 = (const float*)d_in[6];
    const float* b2     = (const float*)d_in[7];
    float*       out    = (float*)d_out;

    const int BLK = 256;
    const int node_grid = (NUM_NODES + BLK - 1) / BLK;     // 3907
    const int quad_grid = (NUM_EDGES / 4 + BLK - 1) / BLK;

    detect_kernel<<<1, 256>>>((const long long*)ei);
    prep_kernel<<<node_grid, BLK>>>(x);
    // CSR build (once per launch; shared by both layers)
    hist_kernel<<<quad_grid, BLK>>>(ei);
    scan1_kernel<<<NBLK, SCAN_BLK>>>();
    scan2_kernel<<<1, SCAN_BLK>>>();
    scan3_kernel<<<NBLK, SCAN_BLK>>>();
    reorder_kernel<<<quad_grid, BLK>>>(ei);
    // Two fused gather+transform layers (no atomics, staged indices)
    gather_kernel<0><<<node_grid, GBLK>>>(Wrel1, Wroot1, b1, nullptr);
    gather_kernel<1><<<node_grid, GBLK>>>(Wrel2, Wroot2, b2, out);
}

// round 8
// speedup vs baseline: 1.2183x; 1.2183x over previous
#include <cuda_runtime.h>

#define NUM_NODES 1000000
#define NUM_EDGES 16000000
#define F  6
#define FP 8   // padded feature width: 32B row = one L2 sector

// Scratch: device globals (no allocation allowed anywhere).
__device__ __align__(128) float g_x8 [NUM_NODES * FP];  // padded x (lanes 6,7 = 0)
__device__ __align__(128) float g_agg[NUM_NODES * FP];  // scatter-add accumulator
__device__ __align__(128) float g_h8 [NUM_NODES * FP];  // padded layer-1 output
__device__ int g_idx_is32;                              // 1 if edge_index is int32

// ---------------------------------------------------------------------------
// detect edge-index dtype (int32 vs int64); runs every launch.
// ---------------------------------------------------------------------------
__global__ void detect_kernel(const long long* __restrict__ ei) {
    __shared__ int bad;
    if (threadIdx.x == 0) bad = 0;
    __syncthreads();
    #pragma unroll
    for (int r = 0; r < 16; r++) {
        long long v = ei[threadIdx.x + r * 256];
        if ((unsigned long long)v >= (unsigned long long)NUM_NODES) bad = 1;
    }
    __syncthreads();
    if (threadIdx.x == 0) g_idx_is32 = bad;
}

// ---------------------------------------------------------------------------
// prep: pad x into g_x8 (zeros in lanes 6,7) and zero g_agg.
// ---------------------------------------------------------------------------
__global__ void prep_kernel(const float* __restrict__ x) {
    int i = blockIdx.x * blockDim.x + threadIdx.x;
    if (i >= NUM_NODES) return;
    const float* xr = x + (size_t)i * F;
    float4* px = reinterpret_cast<float4*>(g_x8 + (size_t)i * FP);
    px[0] = make_float4(xr[0], xr[1], xr[2], xr[3]);
    px[1] = make_float4(xr[4], xr[5], 0.f, 0.f);
    float4 z = make_float4(0.f, 0.f, 0.f, 0.f);
    float4* pa = reinterpret_cast<float4*>(g_agg + (size_t)i * FP);
    pa[0] = z; pa[1] = z;
}

__device__ __forceinline__ void red_add_v4(float* p, float4 v) {
    asm volatile("red.global.add.v4.f32 [%0], {%1, %2, %3, %4};"
                 :: "l"(p), "f"(v.x), "f"(v.y), "f"(v.z), "f"(v.w) : "memory");
}

// ---------------------------------------------------------------------------
// Lane-paired edge scatter. Work item = half-edge: item = 2*e + h.
// Lane pair (2k, 2k+1) handles edge e together: lane h loads feat row half h
// (one uniform LDG.128; the pair shares one 128B line -> HALF the L1tex
// wavefronts of the naive layout) and issues one red.v4 to agg row half h
// (odd half adds zeros into the padding lanes -> harmless).
// 4 half-edges (2 edges) per thread, strided so warp items stay consecutive.
// ---------------------------------------------------------------------------
#define NITEMS (2 * NUM_EDGES)
#define ITEMS_PER_THREAD 4
#define SCAT_THREADS (NITEMS / ITEMS_PER_THREAD)   // 8M

template <int PHASE>
__global__ void scatter_kernel(const void* __restrict__ ei) {
    int gid = blockIdx.x * blockDim.x + threadIdx.x;
    if (gid >= SCAT_THREADS) return;
    const float* feat = (PHASE == 0) ? g_x8 : g_h8;
    const bool is32 = (g_idx_is32 != 0);

    const int* src32 = (const int*)ei;
    const int* dst32 = src32 + NUM_EDGES;
    const long long* src64 = (const long long*)ei;
    const long long* dst64 = src64 + NUM_EDGES;

    unsigned s[ITEMS_PER_THREAD], d[ITEMS_PER_THREAD];
    int      hh[ITEMS_PER_THREAD];
    #pragma unroll
    for (int k = 0; k < ITEMS_PER_THREAD; k++) {
        int item = gid + k * SCAT_THREADS;     // SCAT_THREADS even -> parity fixed
        int e = item >> 1;
        hh[k] = item & 1;
        if (is32) {
            s[k] = (unsigned)__ldcs(src32 + e);
            d[k] = (unsigned)__ldcs(dst32 + e);
        } else {
            s[k] = (unsigned)__ldcs(src64 + e);
            d[k] = (unsigned)__ldcs(dst64 + e);
        }
    }

    float4 v[ITEMS_PER_THREAD];
    bool ok[ITEMS_PER_THREAD];
    #pragma unroll
    for (int k = 0; k < ITEMS_PER_THREAD; k++) {
        ok[k] = (s[k] < NUM_NODES) && (d[k] < NUM_NODES);
        if (ok[k])
            v[k] = *(reinterpret_cast<const float4*>(feat + (size_t)s[k] * FP) + hh[k]);
    }
    #pragma unroll
    for (int k = 0; k < ITEMS_PER_THREAD; k++) {
        if (ok[k])
            red_add_v4(g_agg + (size_t)d[k] * FP + hh[k] * 4, v[k]);
    }
}

// ---------------------------------------------------------------------------
// per-node dense transform (unchanged from the 420us baseline).
// FINAL=false : write padded h into g_h8, re-zero g_agg for layer 2.
// FINAL=true  : argmax (first-max wins = jnp.argmax) -> one-hot.
// ---------------------------------------------------------------------------
template <bool FINAL>
__global__ void transform_kernel(const float* __restrict__ Wrel,
                                 const float* __restrict__ Wroot,
                                 const float* __restrict__ b,
                                 float* __restrict__ out) {
    __shared__ float swr[36], swo[36], sb[6];
    int t = threadIdx.x;
    if (t < 36)        swr[t]      = Wrel[t];
    else if (t < 72)   swo[t - 36] = Wroot[t - 36];
    else if (t < 78)   sb[t - 72]  = b[t - 72];
    __syncthreads();

    int i = blockIdx.x * blockDim.x + t;
    if (i >= NUM_NODES) return;

    const float* in_feat = FINAL ? g_h8 : g_x8;

    const float4* pa = reinterpret_cast<const float4*>(g_agg + (size_t)i * FP);
    float4 a0 = pa[0], a1 = pa[1];
    const float4* px = reinterpret_cast<const float4*>(in_feat + (size_t)i * FP);
    float4 x0 = px[0], x1 = px[1];

    float ag[6] = {a0.x, a0.y, a0.z, a0.w, a1.x, a1.y};
    float xv[6] = {x0.x, x0.y, x0.z, x0.w, x1.x, x1.y};

    float h[6];
    #pragma unroll
    for (int k = 0; k < 6; k++) {
        float acc = sb[k];
        #pragma unroll
        for (int j = 0; j < 6; j++) {
            acc = fmaf(ag[j], swr[k * 6 + j], acc);
            acc = fmaf(xv[j], swo[k * 6 + j], acc);
        }
        h[k] = acc;
    }

    if (!FINAL) {
        float4 z = make_float4(0.f, 0.f, 0.f, 0.f);
        float4* paw = reinterpret_cast<float4*>(g_agg + (size_t)i * FP);
        paw[0] = z; paw[1] = z;
        float4* ph = reinterpret_cast<float4*>(g_h8 + (size_t)i * FP);
        ph[0] = make_float4(h[0], h[1], h[2], h[3]);
        ph[1] = make_float4(h[4], h[5], 0.f, 0.f);
    } else {
        int best = 0; float bv = h[0];
        #pragma unroll
        for (int k = 1; k < 6; k++)
            if (h[k] > bv) { bv = h[k]; best = k; }
        float* po = out + (size_t)i * F;
        #pragma unroll
        for (int k = 0; k < 6; k++)
            po[k] = (k == best) ? 1.f : 0.f;
    }
}

extern "C" void kernel_launch(void* const* d_in, const int* in_sizes, int n_in,
                              void* d_out, int out_size) {
    const float* x      = (const float*)d_in[0];
    const void*  ei     = d_in[1];
    const float* Wrel1  = (const float*)d_in[2];
    const float* Wroot1 = (const float*)d_in[3];
    const float* b1     = (const float*)d_in[4];
    const float* Wrel2  = (const float*)d_in[5];
    const float* Wroot2 = (const float*)d_in[6];
    const float* b2     = (const float*)d_in[7];
    float*       out    = (float*)d_out;

    const int BLK = 256;
    const int node_grid = (NUM_NODES + BLK - 1) / BLK;
    const int scat_grid = (SCAT_THREADS + BLK - 1) / BLK;

    detect_kernel<<<1, 256>>>((const long long*)ei);
    // Layer 1
    prep_kernel<<<node_grid, BLK>>>(x);
    scatter_kernel<0><<<scat_grid, BLK>>>(ei);
    transform_kernel<false><<<node_grid, BLK>>>(Wrel1, Wroot1, b1, nullptr);
    // Layer 2
    scatter_kernel<1><<<scat_grid, BLK>>>(ei);
    transform_kernel<true><<<node_grid, BLK>>>(Wrel2, Wroot2, b2, out);
}